// round 16
// baseline (speedup 1.0000x reference)
#include <cuda_runtime.h>
#include <mma.h>
#include <math.h>
#include <cstdint>

using namespace nvcuda;

#define Nn   768
#define NNt  (768*768)
#define PROJ 1152
#define CATD 2112

#define RS48 0.14433756729740643f   /* 1/sqrt(48) */
#define RS3  0.5773502691896258f    /* 1/sqrt(3)  */
#define RS54 0.13608276348795434f   /* 1/sqrt(54) */

/* ------------------------- scratch (device globals) ---------------------- */
__device__ float g_proj[Nn * PROJ];
__device__ float g_q [Nn * 192];
__device__ float g_k [Nn * 192];
__device__ float g_qp[Nn * 144];
__device__ float g_kp[Nn * 144];
__device__ float g_vc[12 * Nn * 48];        /* packed v(16) || vp(24) || pad8 */
__device__ float g_a [(size_t)12 * NNt];    /* logits -> attn (28.3 MB) */
__device__ float g_ptg[Nn * 12 * 24];       /* o_pt in global frame */
__device__ float g_cat[(size_t)Nn * CATD];

/* ---------------- 3xTF32 split-precision MMA helper ---------------------- */
typedef wmma::fragment<wmma::matrix_a, 16, 16, 8, wmma::precision::tf32, wmma::row_major> FragA;
typedef wmma::fragment<wmma::matrix_b, 16, 16, 8, wmma::precision::tf32, wmma::row_major> FragB;
typedef wmma::fragment<wmma::accumulator, 16, 16, 8, float> FragC;

__device__ __forceinline__ void mma3(FragC& cf,
                                     const float* aptr, int lda,
                                     const float* bptr, int ldb)
{
    FragA ah, al;
    FragB bh, bl;
    wmma::load_matrix_sync(ah, aptr, lda);
    wmma::load_matrix_sync(bh, bptr, ldb);
#pragma unroll
    for (int e = 0; e < ah.num_elements; e++) {
        float v = ah.x[e];
        float h = wmma::__float_to_tf32(v);
        ah.x[e] = h;
        al.x[e] = wmma::__float_to_tf32(v - h);
    }
#pragma unroll
    for (int e = 0; e < bh.num_elements; e++) {
        float v = bh.x[e];
        float h = wmma::__float_to_tf32(v);
        bh.x[e] = h;
        bl.x[e] = wmma::__float_to_tf32(v - h);
    }
    wmma::mma_sync(cf, ah, bl, cf);
    wmma::mma_sync(cf, al, bh, cf);
    wmma::mma_sync(cf, ah, bh, cf);
}

/* ------- K1: projection GEMM 768 x 1152 x 384 (fp32), pack fused --------- */
__device__ __forceinline__ float pick_bias(int o,
    const float* bq, const float* bkv, const float* bqp, const float* bkvp)
{
    if (o < 192) return bq[o];
    if (o < 576) return bkv[o - 192];
    if (o < 720) return bqp[o - 576];
    return bkvp[o - 720];
}

__global__ __launch_bounds__(256) void k_proj_gemm(const float* __restrict__ s,
    const float* __restrict__ Wq,  const float* __restrict__ Wkv,
    const float* __restrict__ Wqp, const float* __restrict__ Wkvp,
    const float* __restrict__ bq,  const float* __restrict__ bkv,
    const float* __restrict__ bqp, const float* __restrict__ bkvp)
{
    __shared__ float s_t[16][65];
    __shared__ float w_t[16][64];
    int o0 = blockIdx.x * 64, i0 = blockIdx.y * 64;
    int t  = threadIdx.x;
    int tx = t % 16, ty = t / 16;
    float acc[4][4];
#pragma unroll
    for (int a = 0; a < 4; a++)
#pragma unroll
        for (int b = 0; b < 4; b++) acc[a][b] = 0.f;

    for (int k0 = 0; k0 < 384; k0 += 16) {
        { int ii = t / 4, kc = (t % 4) * 4;
          float4 sv = *(const float4*)&s[(size_t)(i0 + ii) * 384 + k0 + kc];
          s_t[kc + 0][ii] = sv.x; s_t[kc + 1][ii] = sv.y;
          s_t[kc + 2][ii] = sv.z; s_t[kc + 3][ii] = sv.w; }
        { int kc = t / 16, oo = (t % 16) * 4;
          int o = o0 + oo, r = k0 + kc;
          float4 wv;
          if      (o < 192) wv = *(const float4*)&Wq  [(size_t)r * 192 + o];
          else if (o < 576) wv = *(const float4*)&Wkv [(size_t)r * 384 + (o - 192)];
          else if (o < 720) wv = *(const float4*)&Wqp [(size_t)r * 144 + (o - 576)];
          else              wv = *(const float4*)&Wkvp[(size_t)r * 432 + (o - 720)];
          *(float4*)&w_t[kc][oo] = wv; }
        __syncthreads();
#pragma unroll
        for (int kc = 0; kc < 16; kc++) {
            float sv[4];
#pragma unroll
            for (int a = 0; a < 4; a++) sv[a] = s_t[kc][ty * 4 + a];
            float4 w4 = *(float4*)&w_t[kc][tx * 4];
            float wv[4] = {w4.x, w4.y, w4.z, w4.w};
#pragma unroll
            for (int a = 0; a < 4; a++)
#pragma unroll
                for (int b = 0; b < 4; b++) acc[a][b] += sv[a] * wv[b];
        }
        __syncthreads();
    }
#pragma unroll
    for (int a = 0; a < 4; a++) {
        float4 o4;
        o4.x = acc[a][0] + pick_bias(o0 + tx*4 + 0, bq, bkv, bqp, bkvp);
        o4.y = acc[a][1] + pick_bias(o0 + tx*4 + 1, bq, bkv, bqp, bkvp);
        o4.z = acc[a][2] + pick_bias(o0 + tx*4 + 2, bq, bkv, bqp, bkvp);
        o4.w = acc[a][3] + pick_bias(o0 + tx*4 + 3, bq, bkv, bqp, bkvp);
        *(float4*)&g_proj[(size_t)(i0 + ty * 4 + a) * PROJ + o0 + tx * 4] = o4;
    }
}

/* -------------- K1b: reshape + rigid-frame rotation of points ------------ */
__global__ __launch_bounds__(192) void k_reshape(const float* __restrict__ rot,
                                                 const float* __restrict__ trans)
{
    int i = blockIdx.x, t = threadIdx.x;
    __shared__ float pr[PROJ];
    for (int idx = t; idx < PROJ; idx += 192) pr[idx] = g_proj[(size_t)i * PROJ + idx];
    __syncthreads();

    g_q[(size_t)i * 192 + t] = pr[t];
    for (int o = t; o < 384; o += 192) {
        int h = o / 32, w = o % 32;
        float v = pr[192 + o];
        if (w < 16) g_k[(size_t)i * 192 + h * 16 + w] = v;
        else        g_vc[(size_t)(h * Nn + i) * 48 + (w - 16)] = v;
    }
    for (int o = t; o < 96; o += 192) {
        int h = o / 8, c = 40 + (o % 8);
        g_vc[(size_t)(h * Nn + i) * 48 + c] = 0.f;
    }
    float R0 = rot[i*9+0], R1 = rot[i*9+1], R2 = rot[i*9+2];
    float R3 = rot[i*9+3], R4 = rot[i*9+4], R5 = rot[i*9+5];
    float R6 = rot[i*9+6], R7 = rot[i*9+7], R8 = rot[i*9+8];
    float T0 = trans[i*3+0], T1 = trans[i*3+1], T2 = trans[i*3+2];

    if (t < 48) {
        float v0 = pr[576 + t], v1 = pr[624 + t], v2 = pr[672 + t];
        float x = R0*v0 + R1*v1 + R2*v2 + T0;
        float y = R3*v0 + R4*v1 + R5*v2 + T1;
        float z = R6*v0 + R7*v1 + R8*v2 + T2;
        int base = i * 144 + t * 3;
        g_qp[base] = x; g_qp[base+1] = y; g_qp[base+2] = z;
    }
    if (t < 144) {
        float v0 = pr[720 + t], v1 = pr[864 + t], v2 = pr[1008 + t];
        float x = R0*v0 + R1*v1 + R2*v2 + T0;
        float y = R3*v0 + R4*v1 + R5*v2 + T1;
        float z = R6*v0 + R7*v1 + R8*v2 + T2;
        int h = t / 12, r = t % 12;
        if (r < 4) {
            int base = i * 144 + (h * 4 + r) * 3;
            g_kp[base] = x; g_kp[base+1] = y; g_kp[base+2] = z;
        } else {
            int base = (h * Nn + i) * 48 + 16 + (r - 4) * 3;
            g_vc[base] = x; g_vc[base+1] = y; g_vc[base+2] = z;
        }
    }
}

/* ---- K2a: logits = qk*rs48 + pt + mask + rs3*b_b   (64x64xh tiles) ------ */
__global__ __launch_bounds__(256) void k_logits(const float* __restrict__ mask,
                                                const float* __restrict__ hwraw,
                                                const float* __restrict__ b_b)
{
    __shared__ float q_sT[16][64], k_sT[16][64];
    __shared__ float qp_sT[12][64], kp_sT[12][64];
    __shared__ float mi_s[64], mj_s[64];
    __shared__ float hw_sh, bb_sh;
    int h = blockIdx.z, i0 = blockIdx.y * 64, j0 = blockIdx.x * 64;
    int t = threadIdx.x;

    { int ii = t / 4, c0 = (t % 4) * 4;
      float4 qv = *(const float4*)&g_q[(size_t)(i0 + ii) * 192 + h * 16 + c0];
      q_sT[c0+0][ii] = qv.x; q_sT[c0+1][ii] = qv.y; q_sT[c0+2][ii] = qv.z; q_sT[c0+3][ii] = qv.w;
      float4 kv = *(const float4*)&g_k[(size_t)(j0 + ii) * 192 + h * 16 + c0];
      k_sT[c0+0][ii] = kv.x; k_sT[c0+1][ii] = kv.y; k_sT[c0+2][ii] = kv.z; k_sT[c0+3][ii] = kv.w; }
    if (t < 192) {
      int ii = t / 3, c0 = (t % 3) * 4;
      float4 qv = *(const float4*)&g_qp[(size_t)(i0 + ii) * 144 + h * 12 + c0];
      qp_sT[c0+0][ii] = qv.x; qp_sT[c0+1][ii] = qv.y; qp_sT[c0+2][ii] = qv.z; qp_sT[c0+3][ii] = qv.w;
      float4 kv = *(const float4*)&g_kp[(size_t)(j0 + ii) * 144 + h * 12 + c0];
      kp_sT[c0+0][ii] = kv.x; kp_sT[c0+1][ii] = kv.y; kp_sT[c0+2][ii] = kv.z; kp_sT[c0+3][ii] = kv.w; }
    if (t < 64) { mi_s[t] = mask[i0 + t]; mj_s[t] = mask[j0 + t]; }
    if (t == 0) {
        hw_sh = log1pf(expf(hwraw[h])) * RS54;
        bb_sh = b_b[h] * RS3;
    }
    __syncthreads();

    int tx = t % 16, ty = t / 16;
    float acc[4][4], d2[4][4];
#pragma unroll
    for (int a = 0; a < 4; a++)
#pragma unroll
        for (int b = 0; b < 4; b++) { acc[a][b] = 0.f; d2[a][b] = 0.f; }

#pragma unroll
    for (int c = 0; c < 16; c++) {
        float qr[4];
#pragma unroll
        for (int a = 0; a < 4; a++) qr[a] = q_sT[c][ty * 4 + a];
        float4 k4 = *(float4*)&k_sT[c][tx * 4];
        float kr[4] = {k4.x, k4.y, k4.z, k4.w};
#pragma unroll
        for (int a = 0; a < 4; a++)
#pragma unroll
            for (int b = 0; b < 4; b++) acc[a][b] += qr[a] * kr[b];
    }
#pragma unroll
    for (int p = 0; p < 4; p++) {
        float qx[4], qy[4], qz[4], kx[4], ky[4], kz[4];
#pragma unroll
        for (int a = 0; a < 4; a++) {
            qx[a] = qp_sT[p*3+0][ty*4+a];
            qy[a] = qp_sT[p*3+1][ty*4+a];
            qz[a] = qp_sT[p*3+2][ty*4+a];
        }
#pragma unroll
        for (int b = 0; b < 4; b++) {
            kx[b] = kp_sT[p*3+0][tx*4+b];
            ky[b] = kp_sT[p*3+1][tx*4+b];
            kz[b] = kp_sT[p*3+2][tx*4+b];
        }
#pragma unroll
        for (int a = 0; a < 4; a++)
#pragma unroll
            for (int b = 0; b < 4; b++) {
                float dx = qx[a]-kx[b], dy = qy[a]-ky[b], dz = qz[a]-kz[b];
                d2[a][b] += dx*dx + dy*dy + dz*dz;
            }
    }
    float hw = hw_sh, bb = bb_sh;
#pragma unroll
    for (int a = 0; a < 4; a++) {
        float mi = mi_s[ty * 4 + a];
        float4 o4;
        o4.x = acc[a][0]*RS48 - 0.5f*hw*d2[a][0] + bb + 100000.0f*(mi*mj_s[tx*4+0] - 1.0f);
        o4.y = acc[a][1]*RS48 - 0.5f*hw*d2[a][1] + bb + 100000.0f*(mi*mj_s[tx*4+1] - 1.0f);
        o4.z = acc[a][2]*RS48 - 0.5f*hw*d2[a][2] + bb + 100000.0f*(mi*mj_s[tx*4+2] - 1.0f);
        o4.w = acc[a][3]*RS48 - 0.5f*hw*d2[a][3] + bb + 100000.0f*(mi*mj_s[tx*4+3] - 1.0f);
        *(float4*)&g_a[(size_t)h * NNt + (size_t)(i0 + ty*4 + a) * Nn + j0 + tx*4] = o4;
    }
}

/* ==== K3 v2: FUSED bias + online-softmax + o_pair (fragment-resident) ==== */
#define JC   32
#define ZLD  132
#define NCH  (Nn / JC)                /* 24 */

__global__ __launch_bounds__(256, 3) void k_flash(const float* __restrict__ z,
                                                  const float* __restrict__ ss,
                                                  const float* __restrict__ W_b)
{
    extern __shared__ float sm[];
    float* zb    = sm;                       /* 2 x 32 x 132 = 8448      */
    float* wb    = zb    + 8448;             /* 128 x 20     = 2560      */
    float* part  = wb    + 2560;             /* 8 x 256      = 2048      */
    float* ps    = part  + 2048;             /* 16 x 33      = 528       */
    float* mtab  = ps    + 528;              /* 12 x 24      = 288       */
    float* m_sh  = mtab  + 288;              /* 12                       */
    float* s_sh  = m_sh  + 12;               /* 12                       */
    float* sc_sh = s_sh  + 12;               /* 12                       */
    float* flag  = sc_sh + 12;               /* 1                        */

    int i = blockIdx.x, t = threadIdx.x;
    const float* zrow = z + (size_t)i * Nn * 128;

    for (int idx = t; idx < 128 * 16; idx += 256) {
        int cc = idx / 16, h = idx % 16;
        wb[cc * 20 + h] = (h < 12) ? RS3 * W_b[cc * 12 + h] : 0.f;
    }
    if (t < 12) { m_sh[t] = -1e30f; s_sh[t] = 0.f; }
    if (t < 132) ps[396 + t] = 0.f;          /* zero A-pad rows 12..15   */

    int w = t >> 5, mt = w & 1, kq = w >> 1;
    int lane = t & 31;
    int hsc = t >> 4, l16 = t & 15;
    bool isScalar = (t < 192);

    FragC oacc;
    wmma::fill_fragment(oacc, 0.f);

    int jj_[4], c16_[4];
#pragma unroll
    for (int k2 = 0; k2 < 4; k2++) {
        int sseg = t + k2 * 256;
        jj_[k2]  = sseg >> 5;
        c16_[k2] = sseg & 31;
    }
    float4 pf[4];
#pragma unroll
    for (int k2 = 0; k2 < 4; k2++)
        pf[k2] = *(const float4*)(zrow + jj_[k2] * 128 + c16_[k2] * 4);

    for (int ch = 0; ch < NCH; ch++) {
        float* zs = zb + (ch & 1) * (JC * ZLD);

        /* phase A: commit chunk ch to smem, prefetch ch+1, load logits/ss */
#pragma unroll
        for (int k2 = 0; k2 < 4; k2++)
            *(float4*)(zs + jj_[k2] * ZLD + c16_[k2] * 4) = pf[k2];
        if (ch + 1 < NCH) {
            const float* src = zrow + (size_t)(ch + 1) * JC * 128;
#pragma unroll
            for (int k2 = 0; k2 < 4; k2++)
                pf[k2] = *(const float4*)(src + jj_[k2] * 128 + c16_[k2] * 4);
        }
        float Lg0 = 0.f, Lg1 = 0.f, w0r = 0.f, w1r = 0.f;
        if (isScalar) {
            size_t ab = (size_t)hsc * NNt + (size_t)i * Nn + ch * JC;
            Lg0 = g_a[ab + l16];
            Lg1 = g_a[ab + 16 + l16];
            w0r = ss[(size_t)i * Nn + ch * JC + l16];
            w1r = ss[(size_t)i * Nn + ch * JC + 16 + l16];
        }
        if (t == 0) *flag = 0.f;
        __syncthreads();

        /* phase B: bias wmma (warp -> m-tile mt, k-quarter kq) */
        {
            FragA af; FragB bf; FragC cfb;
            wmma::fill_fragment(cfb, 0.f);
#pragma unroll
            for (int kk = 0; kk < 4; kk++) {
                int k0 = (kq * 4 + kk) * 8;
                wmma::load_matrix_sync(af, zs + mt * 16 * ZLD + k0, ZLD);
#pragma unroll
                for (int e = 0; e < af.num_elements; e++)
                    af.x[e] = wmma::__float_to_tf32(af.x[e]);
                wmma::load_matrix_sync(bf, wb + k0 * 20, 20);
#pragma unroll
                for (int e = 0; e < bf.num_elements; e++)
                    bf.x[e] = wmma::__float_to_tf32(bf.x[e]);
                wmma::mma_sync(cfb, af, bf, cfb);
            }
            wmma::store_matrix_sync(part + w * 256, cfb, 16, wmma::mem_row_major);
        }
        __syncthreads();

        /* phase C: scalar softmax update (threads 0..191) */
        if (isScalar) {
            float b0 = part[0*256 + l16*16 + hsc] + part[2*256 + l16*16 + hsc]
                     + part[4*256 + l16*16 + hsc] + part[6*256 + l16*16 + hsc];
            float b1 = part[1*256 + l16*16 + hsc] + part[3*256 + l16*16 + hsc]
                     + part[5*256 + l16*16 + hsc] + part[7*256 + l16*16 + hsc];
            float L0 = Lg0 + b0, L1 = Lg1 + b1;
            float mc = fmaxf(L0, L1);
#pragma unroll
            for (int o = 8; o; o >>= 1)
                mc = fmaxf(mc, __shfl_xor_sync(0xffffffffu, mc, o));
            float mold = m_sh[hsc];
            float mnew = fmaxf(mold, mc);
            float ww0 = expf(w0r) - 0.99f;
            float ww1 = expf(w1r) - 0.99f;
            float p0 = expf(L0 - mnew) * ww0;
            float p1 = expf(L1 - mnew) * ww1;
            ps[hsc * 33 + l16]      = p0;
            ps[hsc * 33 + 16 + l16] = p1;
            size_t ab = (size_t)hsc * NNt + (size_t)i * Nn + ch * JC;
            g_a[ab + l16]      = p0;
            g_a[ab + 16 + l16] = p1;
            float psum = p0 + p1;
#pragma unroll
            for (int o = 8; o; o >>= 1)
                psum += __shfl_xor_sync(0xffffffffu, psum, o);
            if (l16 == 0) {
                float sc = expf(mold - mnew);
                s_sh[hsc] = s_sh[hsc] * sc + psum;
                m_sh[hsc] = mnew;
                sc_sh[hsc] = sc;
                mtab[hsc * 24 + ch] = mnew;
                if (sc != 1.0f) *flag = 1.f;
            }
        }
        __syncthreads();

        /* phase D: o_pair fragment rescale (rare) + mma3 accumulate */
        if (*flag != 0.f) {
            wmma::store_matrix_sync(part + w * 256, oacc, 16, wmma::mem_row_major);
            __syncwarp();
#pragma unroll
            for (int e = 0; e < 8; e++) {
                int idx = lane * 8 + e;
                int row = idx >> 4;
                float sc = (row < 12) ? sc_sh[row] : 1.f;
                part[w * 256 + idx] *= sc;
            }
            __syncwarp();
            wmma::load_matrix_sync(oacc, part + w * 256, 16, wmma::mem_row_major);
        }
#pragma unroll
        for (int kk = 0; kk < 4; kk++)
            mma3(oacc, ps + kk * 8, 33, zs + kk * 8 * ZLD + w * 16, ZLD);
        __syncthreads();
    }

    /* epilogue */
    if (t < 12) sc_sh[t] = 1.0f / s_sh[t];   /* inv_s */
    __syncthreads();
    for (int idx = t; idx < 288; idx += 256) {
        int h = idx / 24;
        mtab[idx] = expf(mtab[idx] - m_sh[h]) * sc_sh[h];
    }
    wmma::store_matrix_sync(part + w * 256, oacc, 16, wmma::mem_row_major);
    __syncthreads();

    for (int idx = t; idx < 12 * 128; idx += 256) {
        int h = idx / 128, cc = idx % 128;
        int w2 = cc >> 4, cl = cc & 15;
        g_cat[(size_t)i * CATD + 576 + h * 128 + cc] =
            part[w2 * 256 + h * 16 + cl] * sc_sh[h];
    }
    for (int idx = t; idx < 12 * Nn; idx += 256) {
        int h = idx / Nn, j = idx % Nn;
        g_a[(size_t)h * NNt + (size_t)i * Nn + j] *= mtab[h * 24 + (j >> 5)];
    }
}

#define FLASH_DSM ((8448 + 2560 + 2048 + 528 + 288 + 12 + 12 + 12 + 1) * sizeof(float))

/* ------ K4: o / o_pt via 3xtf32 wmma: per head [768 x 48] = a @ vc ------- */
__global__ __launch_bounds__(96) void k_out_ov()
{
    __shared__ float st[16 * 48];
    int i0 = blockIdx.x * 16, h = blockIdx.y;
    int t = threadIdx.x, w = t / 32;

    FragC cf;
    wmma::fill_fragment(cf, 0.f);

    const float* arow = g_a + (size_t)h * NNt + (size_t)i0 * Nn;
    const float* vcb  = g_vc + (size_t)h * Nn * 48 + w * 16;

    for (int k0 = 0; k0 < Nn; k0 += 8)
        mma3(cf, arow + k0, Nn, vcb + (size_t)k0 * 48, 48);

    wmma::store_matrix_sync(st + w * 16, cf, 48, wmma::mem_row_major);
    __syncthreads();

    for (int idx = t; idx < 16 * 40; idx += 96) {
        int r = idx / 40, c = idx % 40;
        float val = st[r * 48 + c];
        int i = i0 + r;
        if (c < 16) g_cat[(size_t)i * CATD + h * 16 + c] = val;
        else        g_ptg[(i * 12 + h) * 24 + (c - 16)]  = val;
    }
}

/* --------- K4b: frame-inverse rotation of o_pt + norms ------------------- */
__global__ __launch_bounds__(96) void k_ptfinish(const float* __restrict__ rot,
                                                 const float* __restrict__ trans)
{
    int i = blockIdx.x, t = threadIdx.x;
    int h = t / 8, p = t % 8;
    const float* pt = &g_ptg[(i * 12 + h) * 24 + p * 3];
    float gx = pt[0] - trans[i*3+0];
    float gy = pt[1] - trans[i*3+1];
    float gz = pt[2] - trans[i*3+2];
    const float* R = &rot[i*9];
    float lx = R[0]*gx + R[3]*gy + R[6]*gz;
    float ly = R[1]*gx + R[4]*gy + R[7]*gz;
    float lz = R[2]*gx + R[5]*gy + R[8]*gz;
    float nrm = sqrtf(lx*lx + ly*ly + lz*lz + 1e-8f);
    size_t base = (size_t)i * CATD;
    int hp = h * 8 + p;
    g_cat[base + 192 + hp] = lx;
    g_cat[base + 288 + hp] = ly;
    g_cat[base + 384 + hp] = lz;
    g_cat[base + 480 + hp] = nrm;
}

/* --------- K6: final GEMM 768 x 384 x 2112 via 3xtf32 wmma --------------- */
__global__ __launch_bounds__(256) void k_final(float* __restrict__ out,
                                               const float* __restrict__ W_out,
                                               const float* __restrict__ b_out)
{
    __shared__ float A_s[64 * 20];
    __shared__ float B_s[16 * 36];
    __shared__ float st[8 * 256];
    int i0 = blockIdx.y * 64, n0 = blockIdx.x * 32;
    int t = threadIdx.x, w = t / 32;
    int wm = w % 4, wn = w / 4;

    FragC cf;
    wmma::fill_fragment(cf, 0.f);

    for (int k0 = 0; k0 < CATD; k0 += 16) {
        __syncthreads();
        { int r = t / 4, kc = (t % 4) * 4;
          *(float4*)&A_s[r * 20 + kc] =
              *(const float4*)&g_cat[(size_t)(i0 + r) * CATD + k0 + kc]; }
        if (t < 128) {
            int r = t / 8, c = (t % 8) * 4;
            *(float4*)&B_s[r * 36 + c] =
                *(const float4*)&W_out[(size_t)(k0 + r) * 384 + n0 + c];
        }
        __syncthreads();
#pragma unroll
        for (int kk = 0; kk < 16; kk += 8)
            mma3(cf, A_s + wm * 16 * 20 + kk, 20, B_s + kk * 36 + wn * 16, 36);
    }
    wmma::store_matrix_sync(&st[w * 256], cf, 16, wmma::mem_row_major);
    __syncthreads();

    for (int idx = t; idx < 64 * 32; idx += 256) {
        int r = idx / 32, c = idx % 32;
        int ww = (c / 16) * 4 + (r / 16);
        float val = st[ww * 256 + (r % 16) * 16 + (c % 16)] + b_out[n0 + c];
        out[(size_t)(i0 + r) * 384 + n0 + c] = val;
    }
}

/* ------------------------------- launch ---------------------------------- */
extern "C" void kernel_launch(void* const* d_in, const int* in_sizes, int n_in,
                              void* d_out, int out_size)
{
    const float* s     = (const float*)d_in[0];
    const float* z     = (const float*)d_in[1];
    const float* rot   = (const float*)d_in[2];
    const float* trans = (const float*)d_in[3];
    const float* mask  = (const float*)d_in[4];
    const float* ss    = (const float*)d_in[5];
    const float* W_q   = (const float*)d_in[6];
    const float* b_q   = (const float*)d_in[7];
    const float* W_kv  = (const float*)d_in[8];
    const float* b_kv  = (const float*)d_in[9];
    const float* W_qp  = (const float*)d_in[10];
    const float* b_qp  = (const float*)d_in[11];
    const float* W_kvp = (const float*)d_in[12];
    const float* b_kvp = (const float*)d_in[13];
    const float* W_b   = (const float*)d_in[14];
    const float* b_b   = (const float*)d_in[15];
    const float* hwts  = (const float*)d_in[16];
    const float* W_out = (const float*)d_in[17];
    const float* b_out = (const float*)d_in[18];
    float* out = (float*)d_out;

    cudaFuncSetAttribute(k_flash,
                         cudaFuncAttributeMaxDynamicSharedMemorySize,
                         (int)FLASH_DSM);

    { dim3 g(PROJ / 64, Nn / 64);
      k_proj_gemm<<<g, 256>>>(s, W_q, W_kv, W_qp, W_kvp,
                              b_q, b_kv, b_qp, b_kvp); }
    k_reshape<<<Nn, 192>>>(rot, trans);
    { dim3 g(Nn / 64, Nn / 64, 12); k_logits<<<g, 256>>>(mask, hwts, b_b); }
    k_flash<<<Nn, 256, FLASH_DSM>>>(z, ss, W_b);
    { dim3 g(Nn / 16, 12); k_out_ov<<<g, 96>>>(); }
    k_ptfinish<<<Nn, 96>>>(rot, trans);
    { dim3 g(384 / 32, Nn / 64); k_final<<<g, 256>>>(out, W_out, b_out); }
}